// round 12
// baseline (speedup 1.0000x reference)
#include <cuda_runtime.h>
#include <cuda_fp16.h>
#include <cstdint>

#define B_   2
#define S_   2048
#define E_   2048
#define H_   16
#define KV_  4
#define D_   128
#define WIN_ 1024

#define MSZ_ (B_ * S_)     // 4096
#define NQ_  (H_ * D_)     // 2048
#define NKV_ (KV_ * D_)    // 512
#define NQKV_ (NQ_ + 2 * NKV_)   // 3072

// ---------------- scratch ----------------
__device__ float g_qkv[(size_t)MSZ_ * NQKV_];   // packed [M, q|k|v] fp32

__device__ __half g_x16 [(size_t)MSZ_ * E_];
__device__ __half g_wp16[(size_t)NQKV_ * E_];   // packed Wq|Wk|Wv
__device__ __half g_wo16[(size_t)E_ * NQ_];
__device__ __half g_ao16[(size_t)MSZ_ * NQ_];
__device__ __half g_q16 [(size_t)MSZ_ * NQ_];
__device__ __half g_k16 [(size_t)MSZ_ * NKV_];
__device__ __half g_v16 [(size_t)MSZ_ * NKV_];

// ---------------- helpers ----------------
__device__ __forceinline__ uint32_t smem_u32(const void* p) {
    uint32_t a;
    asm("{ .reg .u64 t; cvta.to.shared.u64 t, %1; cvt.u32.u64 %0, t; }" : "=r"(a) : "l"(p));
    return a;
}
__device__ __forceinline__ void cpasync16(uint32_t dst, const void* src) {
    asm volatile("cp.async.cg.shared.global [%0], [%1], 16;" :: "r"(dst), "l"(src));
}
#define CP_COMMIT()  asm volatile("cp.async.commit_group;" ::: "memory")
#define CP_WAIT(n)   asm volatile("cp.async.wait_group %0;" :: "n"(n) : "memory")

__device__ __forceinline__ void ldsm4(uint32_t* r, uint32_t addr) {
    asm volatile("ldmatrix.sync.aligned.m8n8.x4.shared.b16 {%0,%1,%2,%3}, [%4];"
                 : "=r"(r[0]), "=r"(r[1]), "=r"(r[2]), "=r"(r[3]) : "r"(addr));
}
__device__ __forceinline__ void ldsm2(uint32_t* r, uint32_t addr) {
    asm volatile("ldmatrix.sync.aligned.m8n8.x2.shared.b16 {%0,%1}, [%2];"
                 : "=r"(r[0]), "=r"(r[1]) : "r"(addr));
}
__device__ __forceinline__ void ldsm4t(uint32_t* r, uint32_t addr) {
    asm volatile("ldmatrix.sync.aligned.m8n8.x4.trans.shared.b16 {%0,%1,%2,%3}, [%4];"
                 : "=r"(r[0]), "=r"(r[1]), "=r"(r[2]), "=r"(r[3]) : "r"(addr));
}
__device__ __forceinline__ void mma16816h(float* d, const uint32_t* a, const uint32_t* b) {
    asm volatile("mma.sync.aligned.m16n8k16.row.col.f32.f16.f16.f32 "
                 "{%0,%1,%2,%3}, {%4,%5,%6,%7}, {%8,%9}, {%0,%1,%2,%3};"
                 : "+f"(d[0]), "+f"(d[1]), "+f"(d[2]), "+f"(d[3])
                 : "r"(a[0]), "r"(a[1]), "r"(a[2]), "r"(a[3]), "r"(b[0]), "r"(b[1]));
}

// ---------------- fused fp32 -> fp16 conversion for all inputs ----------------
// segment sizes in float4 units:
//   x: 2097152 | Wq: 1048576 | Wk: 262144 | Wv: 262144 | Wo: 1048576  (sum 4718592)
#define CVT_TOTAL4 4718592
__global__ void conv_all(const float* __restrict__ x,  const float* __restrict__ Wq,
                         const float* __restrict__ Wk, const float* __restrict__ Wv,
                         const float* __restrict__ Wo,
                         __half* __restrict__ x16, __half* __restrict__ wp16,
                         __half* __restrict__ wo16)
{
    int i = blockIdx.x * 256 + threadIdx.x;
    const float* s; __half* d; int j;
    if (i < 2097152)      { s = x;  d = x16;            j = i; }
    else if (i < 3145728) { s = Wq; d = wp16;           j = i - 2097152; }
    else if (i < 3407872) { s = Wk; d = wp16 + 4194304; j = i - 3145728; }
    else if (i < 3670016) { s = Wv; d = wp16 + 5242880; j = i - 3407872; }
    else                  { s = Wo; d = wo16;           j = i - 3670016; }
    float4 v = ((const float4*)s)[j];
    ((__half2*)d)[j * 2]     = __floats2half2_rn(v.x, v.y);
    ((__half2*)d)[j * 2 + 1] = __floats2half2_rn(v.z, v.w);
}

// ---------------- single-pass fp16 HMMA GEMM (5-stage cp.async pipeline) ----------------
// C[M,N] = A[M,K] @ B[N,K]^T, fp32 accum. If Vout != nullptr, columns >= 2560
// (the V block of the packed QKV output) are ALSO stored as fp16 into Vout.
#define GSTRIDE 40
#define GTILE_B (128 * GSTRIDE * 2)          // 10240
#define GSTAGE_B (2 * GTILE_B)               // 20480 (A + B)
#define GSTAGES 5
#define GEMM_SMEM (GSTAGES * GSTAGE_B)       // 102400 -> still 2 CTA/SM

__global__ void __launch_bounds__(256)
gemm_f16(const __half* __restrict__ A, const __half* __restrict__ Bw,
         float* __restrict__ C, int N, int K, __half* __restrict__ Vout)
{
    extern __shared__ char smem[];
    const uint32_t sb = smem_u32(smem);

    const int tid  = threadIdx.x;
    const int lane = tid & 31, warp = tid >> 5;
    const int wm   = warp >> 2;
    const int wn   = warp & 3;
    const size_t by = (size_t)blockIdx.y * 128;
    const size_t bx = (size_t)blockIdx.x * 128;

    const __half* srcA = A  + by * K;
    const __half* srcB = Bw + bx * K;

    const int r0 = tid >> 2,  c0 = (tid & 3);
    const int r1 = r0 + 64;

    auto issue = [&](int kt, int s) {
        const uint32_t base = sb + (uint32_t)s * GSTAGE_B;
        cpasync16(base + (r0 * GSTRIDE + c0 * 8) * 2, srcA + (size_t)r0 * K + kt * 32 + c0 * 8);
        cpasync16(base + (r1 * GSTRIDE + c0 * 8) * 2, srcA + (size_t)r1 * K + kt * 32 + c0 * 8);
        cpasync16(base + GTILE_B + (r0 * GSTRIDE + c0 * 8) * 2, srcB + (size_t)r0 * K + kt * 32 + c0 * 8);
        cpasync16(base + GTILE_B + (r1 * GSTRIDE + c0 * 8) * 2, srcB + (size_t)r1 * K + kt * 32 + c0 * 8);
    };

    float acc[4][4][4];
#pragma unroll
    for (int mt = 0; mt < 4; ++mt)
#pragma unroll
        for (int nt = 0; nt < 4; ++nt)
#pragma unroll
            for (int e = 0; e < 4; ++e) acc[mt][nt][e] = 0.f;

    const int l2 = lane & 15;
    const int arow = wm * 64 + (lane & 15);
    const int acol0 = (lane >> 4) * 8;
    const int brow = wn * 32 + (l2 & 7);
    const int bcol0 = (l2 >> 3) * 8;

    const int KT = K / 32;
    for (int p = 0; p < 4 && p < KT; ++p) { issue(p, p % GSTAGES); CP_COMMIT(); }

    for (int kt = 0; kt < KT; ++kt) {
        const int rem = KT - 1 - kt;        // groups still outstanding beyond stage kt
        if (rem >= 3)      CP_WAIT(3);
        else if (rem == 2) CP_WAIT(2);
        else if (rem == 1) CP_WAIT(1);
        else               CP_WAIT(0);
        __syncthreads();
        if (kt + 4 < KT) { issue(kt + 4, (kt + 4) % GSTAGES); CP_COMMIT(); }

        const uint32_t base = sb + (uint32_t)(kt % GSTAGES) * GSTAGE_B;
#pragma unroll
        for (int kk = 0; kk < 32; kk += 16) {
            uint32_t af[4][4], bf[4][2];
#pragma unroll
            for (int mt = 0; mt < 4; ++mt)
                ldsm4(af[mt], base + ((arow + mt * 16) * GSTRIDE + kk + acol0) * 2);
#pragma unroll
            for (int nt = 0; nt < 4; ++nt)
                ldsm2(bf[nt], base + GTILE_B + ((brow + nt * 8) * GSTRIDE + kk + bcol0) * 2);
#pragma unroll
            for (int mt = 0; mt < 4; ++mt)
#pragma unroll
                for (int nt = 0; nt < 4; ++nt)
                    mma16816h(acc[mt][nt], af[mt], bf[nt]);
        }
    }

    const bool vtile = (Vout != nullptr) && (bx >= (size_t)(NQ_ + NKV_));
#pragma unroll
    for (int mt = 0; mt < 4; ++mt) {
        const int row = (int)by + wm * 64 + mt * 16 + (lane >> 2);
#pragma unroll
        for (int nt = 0; nt < 4; ++nt) {
            const int col = (int)bx + wn * 32 + nt * 8 + (lane & 3) * 2;
            *(float2*)(C + (size_t)row * N + col)       = make_float2(acc[mt][nt][0], acc[mt][nt][1]);
            *(float2*)(C + (size_t)(row + 8) * N + col) = make_float2(acc[mt][nt][2], acc[mt][nt][3]);
            if (vtile) {
                int vc = col - (NQ_ + NKV_);
                *(__half2*)(Vout + (size_t)row * NKV_ + vc)       = __floats2half2_rn(acc[mt][nt][0], acc[mt][nt][1]);
                *(__half2*)(Vout + (size_t)(row + 8) * NKV_ + vc) = __floats2half2_rn(acc[mt][nt][2], acc[mt][nt][3]);
            }
        }
    }
}

// ---------------- fused RoPE + RMS-norm for Q and K -> fp16 ----------------
// grid = MSZ_*H_ (q rows) + MSZ_*KV_ (k rows), 128 threads.
__global__ void rope_rms_all(const float* __restrict__ qkv,
                             __half* __restrict__ q16, __half* __restrict__ k16,
                             const float* __restrict__ cosb,
                             const float* __restrict__ sinb)
{
    const int row = blockIdx.x;
    int bs, hh, coloff, orow;
    __half* out;
    if (row < MSZ_ * H_) {
        bs = row / H_;  hh = row - bs * H_;  coloff = 0;    out = q16; orow = row;
    } else {
        int r2 = row - MSZ_ * H_;
        bs = r2 / KV_;  hh = r2 - bs * KV_;  coloff = NQ_;  out = k16; orow = r2;
    }
    const int s = bs % S_;
    const float* p = qkv + (size_t)bs * NQKV_ + coloff + hh * D_;
    const int t  = threadIdx.x;
    const int dh = t & 63;

    float c  = cosb[s * 64 + dh];
    float sn = sinb[s * 64 + dh];
    float x1 = p[dh];
    float x2 = p[dh + 64];
    float val = (t < 64) ? (x1 * c + x2 * sn) : (x2 * c - x1 * sn);

    float sq = val * val;
#pragma unroll
    for (int o = 16; o; o >>= 1) sq += __shfl_xor_sync(0xffffffffu, sq, o);
    __shared__ float red[4];
    if ((t & 31) == 0) red[t >> 5] = sq;
    __syncthreads();
    float total = red[0] + red[1] + red[2] + red[3];
    float y = val * rsqrtf(total * (1.0f / 128.0f) + 1.1920929e-7f);
    out[(size_t)orow * D_ + t] = __float2half(y);
}

// ---------------- windowed-causal flash attention (single-pass fp16 HMMA) ----------------
// block: 128 queries x 1 head; 8 warps; double-buffered K/V tiles of 64 keys; 2 CTA/SM.
#define LDH 136
#define KV_TILE_B (64 * LDH * 2)     // 17408
#define Q_TILE_B  (128 * LDH * 2)    // 34816
#define ATTN_SMEM (Q_TILE_B + 4 * KV_TILE_B)   // 104448

__global__ void __launch_bounds__(256, 2)
attn_mma(const __half* __restrict__ q16, const __half* __restrict__ k16,
         const __half* __restrict__ v16, __half* __restrict__ ao)
{
    extern __shared__ char smem[];
    const uint32_t sb  = smem_u32(smem);
    const uint32_t Qb  = sb;
    const uint32_t kvb = sb + Q_TILE_B;

    const int mblk = blockIdx.x, h = blockIdx.y, b = blockIdx.z;
    const int q0 = mblk * 128;
    const int hk = h >> 2;
    const int tid = threadIdx.x, lane = tid & 31, w = tid >> 5;

    // Q tile load (once)
    for (int i = tid; i < 2048; i += 256) {
        int r = i >> 4, c = (i & 15) * 8;
        cpasync16(Qb + (uint32_t)(r * LDH + c) * 2,
                  q16 + ((size_t)(b * S_ + q0 + r) * H_ + h) * D_ + c);
    }
    CP_COMMIT();

    float o_acc[16][4];
#pragma unroll
    for (int nt = 0; nt < 16; ++nt)
#pragma unroll
        for (int e = 0; e < 4; ++e) o_acc[nt][e] = 0.f;
    float m_lo = -1e30f, m_hi = -1e30f, l_lo = 0.f, l_hi = 0.f;

    const float scale = 0.08838834764831845f;
    const int t_first = (2 * mblk - 16 > 0) ? (2 * mblk - 16) : 0;
    const int t_last  = 2 * mblk + 1;
    const int lane2 = lane & 15;

    auto issue_kv = [&](int t, int s) {
        const uint32_t base = kvb + (uint32_t)s * 2 * KV_TILE_B;
        for (int i = tid; i < 1024; i += 256) {
            int r = i >> 4, c = (i & 15) * 8;
            size_t g = ((size_t)(b * S_ + t * 64 + r) * KV_ + hk) * D_ + c;
            uint32_t o = (uint32_t)(r * LDH + c) * 2;
            cpasync16(base + o, k16 + g);
            cpasync16(base + KV_TILE_B + o, v16 + g);
        }
    };
    issue_kv(t_first, t_first & 1);
    CP_COMMIT();

    const uint32_t a_off = (uint32_t)((w * 16 + (lane & 15)) * LDH + (lane >> 4) * 8) * 2;
    const int i_lo = q0 + w * 16 + (lane >> 2);
    const int i_hi = i_lo + 8;

    for (int t = t_first; t <= t_last; ++t) {
        const int j0 = t * 64;
        __syncthreads();                       // stage being overwritten is free
        if (t < t_last) { issue_kv(t + 1, (t + 1) & 1); CP_COMMIT(); CP_WAIT(1); }
        else            { CP_WAIT(0); }
        __syncthreads();

        const uint32_t Kb = kvb + (uint32_t)(t & 1) * 2 * KV_TILE_B;
        const uint32_t Vb = Kb + KV_TILE_B;

        // ---- S = Q K^T ----
        float s[8][4];
#pragma unroll
        for (int nt = 0; nt < 8; ++nt)
#pragma unroll
            for (int e = 0; e < 4; ++e) s[nt][e] = 0.f;

#pragma unroll
        for (int kk = 0; kk < 128; kk += 16) {
            uint32_t aq[4];
            ldsm4(aq, Qb + a_off + kk * 2);
#pragma unroll
            for (int nt = 0; nt < 8; ++nt) {
                uint32_t bk[2];
                ldsm2(bk, Kb + (uint32_t)((nt * 8 + (lane2 & 7)) * LDH + kk + ((lane2 >> 3) & 1) * 8) * 2);
                mma16816h(s[nt], aq, bk);
            }
        }

        // ---- masked online softmax ----
        float mx_lo = -1e30f, mx_hi = -1e30f;
#pragma unroll
        for (int nt = 0; nt < 8; ++nt) {
            int jb = j0 + nt * 8 + (lane & 3) * 2;
            bool v0 = (jb     <= i_lo) && (i_lo - jb     < WIN_);
            bool v1 = (jb + 1 <= i_lo) && (i_lo - jb - 1 < WIN_);
            bool v2 = (jb     <= i_hi) && (i_hi - jb     < WIN_);
            bool v3 = (jb + 1 <= i_hi) && (i_hi - jb - 1 < WIN_);
            s[nt][0] = v0 ? s[nt][0] * scale : -1e30f;
            s[nt][1] = v1 ? s[nt][1] * scale : -1e30f;
            s[nt][2] = v2 ? s[nt][2] * scale : -1e30f;
            s[nt][3] = v3 ? s[nt][3] * scale : -1e30f;
            mx_lo = fmaxf(mx_lo, fmaxf(s[nt][0], s[nt][1]));
            mx_hi = fmaxf(mx_hi, fmaxf(s[nt][2], s[nt][3]));
        }
        mx_lo = fmaxf(mx_lo, __shfl_xor_sync(0xffffffffu, mx_lo, 1));
        mx_lo = fmaxf(mx_lo, __shfl_xor_sync(0xffffffffu, mx_lo, 2));
        mx_hi = fmaxf(mx_hi, __shfl_xor_sync(0xffffffffu, mx_hi, 1));
        mx_hi = fmaxf(mx_hi, __shfl_xor_sync(0xffffffffu, mx_hi, 2));

        float mn_lo = fmaxf(m_lo, mx_lo), mn_hi = fmaxf(m_hi, mx_hi);
        float al_lo = __expf(m_lo - mn_lo), al_hi = __expf(m_hi - mn_hi);
        float sum_lo = 0.f, sum_hi = 0.f;
#pragma unroll
        for (int nt = 0; nt < 8; ++nt) {
            s[nt][0] = __expf(s[nt][0] - mn_lo);
            s[nt][1] = __expf(s[nt][1] - mn_lo);
            s[nt][2] = __expf(s[nt][2] - mn_hi);
            s[nt][3] = __expf(s[nt][3] - mn_hi);
            sum_lo += s[nt][0] + s[nt][1];
            sum_hi += s[nt][2] + s[nt][3];
        }
        sum_lo += __shfl_xor_sync(0xffffffffu, sum_lo, 1);
        sum_lo += __shfl_xor_sync(0xffffffffu, sum_lo, 2);
        sum_hi += __shfl_xor_sync(0xffffffffu, sum_hi, 1);
        sum_hi += __shfl_xor_sync(0xffffffffu, sum_hi, 2);
        l_lo = l_lo * al_lo + sum_lo;  m_lo = mn_lo;
        l_hi = l_hi * al_hi + sum_hi;  m_hi = mn_hi;
#pragma unroll
        for (int nt = 0; nt < 16; ++nt) {
            o_acc[nt][0] *= al_lo; o_acc[nt][1] *= al_lo;
            o_acc[nt][2] *= al_hi; o_acc[nt][3] *= al_hi;
        }

        // ---- O += P V ----
#pragma unroll
        for (int kc = 0; kc < 4; ++kc) {
            uint32_t ap[4];
            __half2 p0 = __floats2half2_rn(s[2*kc][0],   s[2*kc][1]);
            __half2 p1 = __floats2half2_rn(s[2*kc][2],   s[2*kc][3]);
            __half2 p2 = __floats2half2_rn(s[2*kc+1][0], s[2*kc+1][1]);
            __half2 p3 = __floats2half2_rn(s[2*kc+1][2], s[2*kc+1][3]);
            ap[0] = *(uint32_t*)&p0; ap[1] = *(uint32_t*)&p1;
            ap[2] = *(uint32_t*)&p2; ap[3] = *(uint32_t*)&p3;

            uint32_t vr = (uint32_t)(kc * 16 + (lane & 7) + ((lane >> 3) & 1) * 8) * LDH
                        + (uint32_t)((lane >> 4) * 8);
#pragma unroll
            for (int dt = 0; dt < 8; ++dt) {
                uint32_t bv[4];
                ldsm4t(bv, Vb + (vr + dt * 16) * 2);
                mma16816h(o_acc[2*dt],   ap, bv);
                mma16816h(o_acc[2*dt+1], ap, bv + 2);
            }
        }
    }

    // ---- epilogue: normalize, write fp16 ----
    float inv_lo = 1.0f / l_lo, inv_hi = 1.0f / l_hi;
#pragma unroll
    for (int nt = 0; nt < 16; ++nt) {
        int c = nt * 8 + (lane & 3) * 2;
        size_t glo = ((size_t)(b * S_ + i_lo) * H_ + h) * D_ + c;
        size_t ghi = ((size_t)(b * S_ + i_hi) * H_ + h) * D_ + c;
        *(__half2*)(ao + glo) = __floats2half2_rn(o_acc[nt][0] * inv_lo, o_acc[nt][1] * inv_lo);
        *(__half2*)(ao + ghi) = __floats2half2_rn(o_acc[nt][2] * inv_hi, o_acc[nt][3] * inv_hi);
    }
}

// ---------------- launch ----------------
extern "C" void kernel_launch(void* const* d_in, const int* in_sizes, int n_in,
                              void* d_out, int out_size)
{
    (void)in_sizes; (void)n_in; (void)out_size;
    const float* x    = (const float*)d_in[0];
    const float* cosb = (const float*)d_in[1];
    const float* sinb = (const float*)d_in[2];
    const float* Wq   = (const float*)d_in[3];
    const float* Wk   = (const float*)d_in[4];
    const float* Wv   = (const float*)d_in[5];
    const float* Wo   = (const float*)d_in[6];
    float* out = (float*)d_out;

    float* qkv;
    cudaGetSymbolAddress((void**)&qkv, g_qkv);
    __half *x16, *wp16, *wo16, *ao16, *q16, *k16, *v16;
    cudaGetSymbolAddress((void**)&x16,  g_x16);
    cudaGetSymbolAddress((void**)&wp16, g_wp16);
    cudaGetSymbolAddress((void**)&wo16, g_wo16);
    cudaGetSymbolAddress((void**)&ao16, g_ao16);
    cudaGetSymbolAddress((void**)&q16,  g_q16);
    cudaGetSymbolAddress((void**)&k16,  g_k16);
    cudaGetSymbolAddress((void**)&v16,  g_v16);

    const int M = MSZ_;   // 4096
    cudaFuncSetAttribute(gemm_f16, cudaFuncAttributeMaxDynamicSharedMemorySize, GEMM_SMEM);
    cudaFuncSetAttribute(attn_mma, cudaFuncAttributeMaxDynamicSharedMemorySize, ATTN_SMEM);

    // 1) fused fp16 conversions (x, Wq|Wk|Wv packed, Wo)
    conv_all<<<CVT_TOTAL4 / 256, 256>>>(x, Wq, Wk, Wv, Wo, x16, wp16, wo16);

    // 2) fused QKV projection; epilogue writes V columns directly as fp16
    gemm_f16<<<dim3(NQKV_ / 128, M / 128), 256, GEMM_SMEM>>>(x16, wp16, qkv, NQKV_, E_, v16);

    // 3) fused rope+rms for Q and K
    rope_rms_all<<<M * (H_ + KV_), 128>>>(qkv, q16, k16, cosb, sinb);

    // 4) attention (fp16 single-pass, 2 CTA/SM)
    attn_mma<<<dim3(S_ / 128, H_, B_), 256, ATTN_SMEM>>>(q16, k16, v16, ao16);

    // 5) output projection
    gemm_f16<<<dim3(E_ / 128, M / 128), 256, GEMM_SMEM>>>(ao16, wo16, out, E_, NQ_, nullptr);
}

// round 13
// speedup vs baseline: 1.5172x; 1.5172x over previous
#include <cuda_runtime.h>
#include <cuda_fp16.h>
#include <cstdint>

#define B_   2
#define S_   2048
#define E_   2048
#define H_   16
#define KV_  4
#define D_   128
#define WIN_ 1024

#define MSZ_ (B_ * S_)     // 4096
#define NQ_  (H_ * D_)     // 2048
#define NKV_ (KV_ * D_)    // 512
#define NQKV_ (NQ_ + 2 * NKV_)   // 3072

// ---------------- scratch ----------------
__device__ float g_qkv[(size_t)MSZ_ * NQKV_];   // packed [M, q|k|v] fp32

__device__ __half g_x16 [(size_t)MSZ_ * E_];
__device__ __half g_wp16[(size_t)NQKV_ * E_];   // packed Wq|Wk|Wv
__device__ __half g_wo16[(size_t)E_ * NQ_];
__device__ __half g_ao16[(size_t)MSZ_ * NQ_];
__device__ __half g_q16 [(size_t)MSZ_ * NQ_];
__device__ __half g_k16 [(size_t)MSZ_ * NKV_];
__device__ __half g_v16 [(size_t)MSZ_ * NKV_];

// ---------------- helpers ----------------
__device__ __forceinline__ uint32_t smem_u32(const void* p) {
    uint32_t a;
    asm("{ .reg .u64 t; cvta.to.shared.u64 t, %1; cvt.u32.u64 %0, t; }" : "=r"(a) : "l"(p));
    return a;
}
__device__ __forceinline__ void cpasync16(uint32_t dst, const void* src) {
    asm volatile("cp.async.cg.shared.global [%0], [%1], 16;" :: "r"(dst), "l"(src));
}
#define CP_COMMIT()  asm volatile("cp.async.commit_group;" ::: "memory")
#define CP_WAIT(n)   asm volatile("cp.async.wait_group %0;" :: "n"(n) : "memory")

__device__ __forceinline__ void ldsm4(uint32_t* r, uint32_t addr) {
    asm volatile("ldmatrix.sync.aligned.m8n8.x4.shared.b16 {%0,%1,%2,%3}, [%4];"
                 : "=r"(r[0]), "=r"(r[1]), "=r"(r[2]), "=r"(r[3]) : "r"(addr));
}
__device__ __forceinline__ void ldsm2(uint32_t* r, uint32_t addr) {
    asm volatile("ldmatrix.sync.aligned.m8n8.x2.shared.b16 {%0,%1}, [%2];"
                 : "=r"(r[0]), "=r"(r[1]) : "r"(addr));
}
__device__ __forceinline__ void ldsm4t(uint32_t* r, uint32_t addr) {
    asm volatile("ldmatrix.sync.aligned.m8n8.x4.trans.shared.b16 {%0,%1,%2,%3}, [%4];"
                 : "=r"(r[0]), "=r"(r[1]), "=r"(r[2]), "=r"(r[3]) : "r"(addr));
}
__device__ __forceinline__ void mma16816h(float* d, const uint32_t* a, const uint32_t* b) {
    asm volatile("mma.sync.aligned.m16n8k16.row.col.f32.f16.f16.f32 "
                 "{%0,%1,%2,%3}, {%4,%5,%6,%7}, {%8,%9}, {%0,%1,%2,%3};"
                 : "+f"(d[0]), "+f"(d[1]), "+f"(d[2]), "+f"(d[3])
                 : "r"(a[0]), "r"(a[1]), "r"(a[2]), "r"(a[3]), "r"(b[0]), "r"(b[1]));
}

// ---------------- fused fp32 -> fp16 conversion for all inputs ----------------
#define CVT_TOTAL4 4718592
__global__ void conv_all(const float* __restrict__ x,  const float* __restrict__ Wq,
                         const float* __restrict__ Wk, const float* __restrict__ Wv,
                         const float* __restrict__ Wo,
                         __half* __restrict__ x16, __half* __restrict__ wp16,
                         __half* __restrict__ wo16)
{
    int i = blockIdx.x * 256 + threadIdx.x;
    const float* s; __half* d; int j;
    if (i < 2097152)      { s = x;  d = x16;            j = i; }
    else if (i < 3145728) { s = Wq; d = wp16;           j = i - 2097152; }
    else if (i < 3407872) { s = Wk; d = wp16 + 4194304; j = i - 3145728; }
    else if (i < 3670016) { s = Wv; d = wp16 + 5242880; j = i - 3407872; }
    else                  { s = Wo; d = wo16;           j = i - 3670016; }
    float4 v = ((const float4*)s)[j];
    ((__half2*)d)[j * 2]     = __floats2half2_rn(v.x, v.y);
    ((__half2*)d)[j * 2 + 1] = __floats2half2_rn(v.z, v.w);
}

// V out of packed QKV (strided read at col NQ_+NKV_) -> fp16
__global__ void conv_v(const float* __restrict__ qkv, __half* __restrict__ v16)
{
    int i = blockIdx.x * blockDim.x + threadIdx.x;
    if (i >= MSZ_ * 128) return;
    int row = i >> 7, c4 = (i & 127) * 4;
    float4 v = *(const float4*)(qkv + (size_t)row * NQKV_ + (NQ_ + NKV_) + c4);
    size_t o = ((size_t)row * NKV_ + c4) >> 1;
    ((__half2*)v16)[o]     = __floats2half2_rn(v.x, v.y);
    ((__half2*)v16)[o + 1] = __floats2half2_rn(v.z, v.w);
}

// ---------------- single-pass fp16 HMMA GEMM (4-stage cp.async pipeline, R11-exact) ----------------
#define GSTRIDE 40
#define GTILE_B (128 * GSTRIDE * 2)          // 10240
#define GSTAGE_B (2 * GTILE_B)               // 20480 (A + B)
#define GEMM_SMEM (4 * GSTAGE_B)             // 81920 -> 2 CTA/SM

__global__ void __launch_bounds__(256)
gemm_f16(const __half* __restrict__ A, const __half* __restrict__ Bw,
         float* __restrict__ C, int N, int K)
{
    extern __shared__ char smem[];
    const uint32_t sb = smem_u32(smem);

    const int tid  = threadIdx.x;
    const int lane = tid & 31, warp = tid >> 5;
    const int wm   = warp >> 2;
    const int wn   = warp & 3;
    const size_t by = (size_t)blockIdx.y * 128;
    const size_t bx = (size_t)blockIdx.x * 128;

    const __half* srcA = A  + by * K;
    const __half* srcB = Bw + bx * K;

    const int r0 = tid >> 2,  c0 = (tid & 3);
    const int r1 = r0 + 64;

    auto issue = [&](int kt, int s) {
        const uint32_t base = sb + (uint32_t)s * GSTAGE_B;
        cpasync16(base + (r0 * GSTRIDE + c0 * 8) * 2, srcA + (size_t)r0 * K + kt * 32 + c0 * 8);
        cpasync16(base + (r1 * GSTRIDE + c0 * 8) * 2, srcA + (size_t)r1 * K + kt * 32 + c0 * 8);
        cpasync16(base + GTILE_B + (r0 * GSTRIDE + c0 * 8) * 2, srcB + (size_t)r0 * K + kt * 32 + c0 * 8);
        cpasync16(base + GTILE_B + (r1 * GSTRIDE + c0 * 8) * 2, srcB + (size_t)r1 * K + kt * 32 + c0 * 8);
    };

    float acc[4][4][4];
#pragma unroll
    for (int mt = 0; mt < 4; ++mt)
#pragma unroll
        for (int nt = 0; nt < 4; ++nt)
#pragma unroll
            for (int e = 0; e < 4; ++e) acc[mt][nt][e] = 0.f;

    const int l2 = lane & 15;
    const int arow = wm * 64 + (lane & 15);
    const int acol0 = (lane >> 4) * 8;
    const int brow = wn * 32 + (l2 & 7);
    const int bcol0 = (l2 >> 3) * 8;

    const int KT = K / 32;
    for (int p = 0; p < 3 && p < KT; ++p) { issue(p, p & 3); CP_COMMIT(); }

    for (int kt = 0; kt < KT; ++kt) {
        if (kt + 2 < KT)      CP_WAIT(2);
        else if (kt + 1 < KT) CP_WAIT(1);
        else                  CP_WAIT(0);
        __syncthreads();
        if (kt + 3 < KT) { issue(kt + 3, (kt + 3) & 3); CP_COMMIT(); }

        const uint32_t base = sb + (uint32_t)(kt & 3) * GSTAGE_B;
#pragma unroll
        for (int kk = 0; kk < 32; kk += 16) {
            uint32_t af[4][4], bf[4][2];
#pragma unroll
            for (int mt = 0; mt < 4; ++mt)
                ldsm4(af[mt], base + ((arow + mt * 16) * GSTRIDE + kk + acol0) * 2);
#pragma unroll
            for (int nt = 0; nt < 4; ++nt)
                ldsm2(bf[nt], base + GTILE_B + ((brow + nt * 8) * GSTRIDE + kk + bcol0) * 2);
#pragma unroll
            for (int mt = 0; mt < 4; ++mt)
#pragma unroll
                for (int nt = 0; nt < 4; ++nt)
                    mma16816h(acc[mt][nt], af[mt], bf[nt]);
        }
    }

#pragma unroll
    for (int mt = 0; mt < 4; ++mt) {
        const int row = (int)by + wm * 64 + mt * 16 + (lane >> 2);
#pragma unroll
        for (int nt = 0; nt < 4; ++nt) {
            const int col = (int)bx + wn * 32 + nt * 8 + (lane & 3) * 2;
            *(float2*)(C + (size_t)row * N + col)       = make_float2(acc[mt][nt][0], acc[mt][nt][1]);
            *(float2*)(C + (size_t)(row + 8) * N + col) = make_float2(acc[mt][nt][2], acc[mt][nt][3]);
        }
    }
}

// ---------------- fused RoPE + RMS-norm for Q and K -> fp16 ----------------
__global__ void rope_rms_all(const float* __restrict__ qkv,
                             __half* __restrict__ q16, __half* __restrict__ k16,
                             const float* __restrict__ cosb,
                             const float* __restrict__ sinb)
{
    const int row = blockIdx.x;
    int bs, hh, coloff, orow;
    __half* out;
    if (row < MSZ_ * H_) {
        bs = row / H_;  hh = row - bs * H_;  coloff = 0;    out = q16; orow = row;
    } else {
        int r2 = row - MSZ_ * H_;
        bs = r2 / KV_;  hh = r2 - bs * KV_;  coloff = NQ_;  out = k16; orow = r2;
    }
    const int s = bs % S_;
    const float* p = qkv + (size_t)bs * NQKV_ + coloff + hh * D_;
    const int t  = threadIdx.x;
    const int dh = t & 63;

    float c  = cosb[s * 64 + dh];
    float sn = sinb[s * 64 + dh];
    float x1 = p[dh];
    float x2 = p[dh + 64];
    float val = (t < 64) ? (x1 * c + x2 * sn) : (x2 * c - x1 * sn);

    float sq = val * val;
#pragma unroll
    for (int o = 16; o; o >>= 1) sq += __shfl_xor_sync(0xffffffffu, sq, o);
    __shared__ float red[4];
    if ((t & 31) == 0) red[t >> 5] = sq;
    __syncthreads();
    float total = red[0] + red[1] + red[2] + red[3];
    float y = val * rsqrtf(total * (1.0f / 128.0f) + 1.1920929e-7f);
    out[(size_t)orow * D_ + t] = __float2half(y);
}

// ---------------- windowed-causal flash attention (single-pass fp16 HMMA) ----------------
// block: 128 queries x 1 head; 8 warps; double-buffered K/V tiles of 64 keys; 2 CTA/SM.
// QK K-operand loaded via paired ldsm4 (two n-tiles per instruction).
#define LDH 136
#define KV_TILE_B (64 * LDH * 2)     // 17408
#define Q_TILE_B  (128 * LDH * 2)    // 34816
#define ATTN_SMEM (Q_TILE_B + 4 * KV_TILE_B)   // 104448

__global__ void __launch_bounds__(256, 2)
attn_mma(const __half* __restrict__ q16, const __half* __restrict__ k16,
         const __half* __restrict__ v16, __half* __restrict__ ao)
{
    extern __shared__ char smem[];
    const uint32_t sb  = smem_u32(smem);
    const uint32_t Qb  = sb;
    const uint32_t kvb = sb + Q_TILE_B;

    const int mblk = blockIdx.x, h = blockIdx.y, b = blockIdx.z;
    const int q0 = mblk * 128;
    const int hk = h >> 2;
    const int tid = threadIdx.x, lane = tid & 31, w = tid >> 5;

    // Q tile load (once)
    for (int i = tid; i < 2048; i += 256) {
        int r = i >> 4, c = (i & 15) * 8;
        cpasync16(Qb + (uint32_t)(r * LDH + c) * 2,
                  q16 + ((size_t)(b * S_ + q0 + r) * H_ + h) * D_ + c);
    }
    CP_COMMIT();

    float o_acc[16][4];
#pragma unroll
    for (int nt = 0; nt < 16; ++nt)
#pragma unroll
        for (int e = 0; e < 4; ++e) o_acc[nt][e] = 0.f;
    float m_lo = -1e30f, m_hi = -1e30f, l_lo = 0.f, l_hi = 0.f;

    const float scale = 0.08838834764831845f;
    const int t_first = (2 * mblk - 16 > 0) ? (2 * mblk - 16) : 0;
    const int t_last  = 2 * mblk + 1;

    auto issue_kv = [&](int t, int s) {
        const uint32_t base = kvb + (uint32_t)s * 2 * KV_TILE_B;
        for (int i = tid; i < 1024; i += 256) {
            int r = i >> 4, c = (i & 15) * 8;
            size_t g = ((size_t)(b * S_ + t * 64 + r) * KV_ + hk) * D_ + c;
            uint32_t o = (uint32_t)(r * LDH + c) * 2;
            cpasync16(base + o, k16 + g);
            cpasync16(base + KV_TILE_B + o, v16 + g);
        }
    };
    issue_kv(t_first, t_first & 1);
    CP_COMMIT();

    const uint32_t a_off = (uint32_t)((w * 16 + (lane & 15)) * LDH + (lane >> 4) * 8) * 2;
    // paired-K ldsm4 addressing: lanes 0-15 -> n-tile nt, lanes 16-31 -> n-tile nt+1
    const int kr = (lane & 7) + ((lane >> 4) << 3);       // row within 16-row pair
    const int kcsel = ((lane >> 3) & 1) << 3;             // col half
    const uint32_t k_off = (uint32_t)(kr * LDH + kcsel) * 2;
    const int i_lo = q0 + w * 16 + (lane >> 2);
    const int i_hi = i_lo + 8;

    for (int t = t_first; t <= t_last; ++t) {
        const int j0 = t * 64;
        __syncthreads();                       // stage being overwritten is free
        if (t < t_last) { issue_kv(t + 1, (t + 1) & 1); CP_COMMIT(); CP_WAIT(1); }
        else            { CP_WAIT(0); }
        __syncthreads();

        const uint32_t Kb = kvb + (uint32_t)(t & 1) * 2 * KV_TILE_B;
        const uint32_t Vb = Kb + KV_TILE_B;

        // ---- S = Q K^T (paired ldsm4 for K) ----
        float s[8][4];
#pragma unroll
        for (int nt = 0; nt < 8; ++nt)
#pragma unroll
            for (int e = 0; e < 4; ++e) s[nt][e] = 0.f;

#pragma unroll
        for (int kk = 0; kk < 128; kk += 16) {
            uint32_t aq[4];
            ldsm4(aq, Qb + a_off + kk * 2);
#pragma unroll
            for (int nt = 0; nt < 8; nt += 2) {
                uint32_t bk[4];
                ldsm4(bk, Kb + k_off + (uint32_t)(nt * 8 * LDH + kk) * 2);
                mma16816h(s[nt],     aq, bk);
                mma16816h(s[nt + 1], aq, bk + 2);
            }
        }

        // ---- masked online softmax ----
        float mx_lo = -1e30f, mx_hi = -1e30f;
#pragma unroll
        for (int nt = 0; nt < 8; ++nt) {
            int jb = j0 + nt * 8 + (lane & 3) * 2;
            bool v0 = (jb     <= i_lo) && (i_lo - jb     < WIN_);
            bool v1 = (jb + 1 <= i_lo) && (i_lo - jb - 1 < WIN_);
            bool v2 = (jb     <= i_hi) && (i_hi - jb     < WIN_);
            bool v3 = (jb + 1 <= i_hi) && (i_hi - jb - 1 < WIN_);
            s[nt][0] = v0 ? s[nt][0] * scale : -1e30f;
            s[nt][1] = v1 ? s[nt][1] * scale : -1e30f;
            s[nt][2] = v2 ? s[nt][2] * scale : -1e30f;
            s[nt][3] = v3 ? s[nt][3] * scale : -1e30f;
            mx_lo = fmaxf(mx_lo, fmaxf(s[nt][0], s[nt][1]));
            mx_hi = fmaxf(mx_hi, fmaxf(s[nt][2], s[nt][3]));
        }
        mx_lo = fmaxf(mx_lo, __shfl_xor_sync(0xffffffffu, mx_lo, 1));
        mx_lo = fmaxf(mx_lo, __shfl_xor_sync(0xffffffffu, mx_lo, 2));
        mx_hi = fmaxf(mx_hi, __shfl_xor_sync(0xffffffffu, mx_hi, 1));
        mx_hi = fmaxf(mx_hi, __shfl_xor_sync(0xffffffffu, mx_hi, 2));

        float mn_lo = fmaxf(m_lo, mx_lo), mn_hi = fmaxf(m_hi, mx_hi);
        float al_lo = __expf(m_lo - mn_lo), al_hi = __expf(m_hi - mn_hi);
        float sum_lo = 0.f, sum_hi = 0.f;
#pragma unroll
        for (int nt = 0; nt < 8; ++nt) {
            s[nt][0] = __expf(s[nt][0] - mn_lo);
            s[nt][1] = __expf(s[nt][1] - mn_lo);
            s[nt][2] = __expf(s[nt][2] - mn_hi);
            s[nt][3] = __expf(s[nt][3] - mn_hi);
            sum_lo += s[nt][0] + s[nt][1];
            sum_hi += s[nt][2] + s[nt][3];
        }
        sum_lo += __shfl_xor_sync(0xffffffffu, sum_lo, 1);
        sum_lo += __shfl_xor_sync(0xffffffffu, sum_lo, 2);
        sum_hi += __shfl_xor_sync(0xffffffffu, sum_hi, 1);
        sum_hi += __shfl_xor_sync(0xffffffffu, sum_hi, 2);
        l_lo = l_lo * al_lo + sum_lo;  m_lo = mn_lo;
        l_hi = l_hi * al_hi + sum_hi;  m_hi = mn_hi;
#pragma unroll
        for (int nt = 0; nt < 16; ++nt) {
            o_acc[nt][0] *= al_lo; o_acc[nt][1] *= al_lo;
            o_acc[nt][2] *= al_hi; o_acc[nt][3] *= al_hi;
        }

        // ---- O += P V ----
#pragma unroll
        for (int kc = 0; kc < 4; ++kc) {
            uint32_t ap[4];
            __half2 p0 = __floats2half2_rn(s[2*kc][0],   s[2*kc][1]);
            __half2 p1 = __floats2half2_rn(s[2*kc][2],   s[2*kc][3]);
            __half2 p2 = __floats2half2_rn(s[2*kc+1][0], s[2*kc+1][1]);
            __half2 p3 = __floats2half2_rn(s[2*kc+1][2], s[2*kc+1][3]);
            ap[0] = *(uint32_t*)&p0; ap[1] = *(uint32_t*)&p1;
            ap[2] = *(uint32_t*)&p2; ap[3] = *(uint32_t*)&p3;

            uint32_t vr = (uint32_t)(kc * 16 + (lane & 7) + ((lane >> 3) & 1) * 8) * LDH
                        + (uint32_t)((lane >> 4) * 8);
#pragma unroll
            for (int dt = 0; dt < 8; ++dt) {
                uint32_t bv[4];
                ldsm4t(bv, Vb + (vr + dt * 16) * 2);
                mma16816h(o_acc[2*dt],   ap, bv);
                mma16816h(o_acc[2*dt+1], ap, bv + 2);
            }
        }
    }

    // ---- epilogue: normalize, write fp16 ----
    float inv_lo = 1.0f / l_lo, inv_hi = 1.0f / l_hi;
#pragma unroll
    for (int nt = 0; nt < 16; ++nt) {
        int c = nt * 8 + (lane & 3) * 2;
        size_t glo = ((size_t)(b * S_ + i_lo) * H_ + h) * D_ + c;
        size_t ghi = ((size_t)(b * S_ + i_hi) * H_ + h) * D_ + c;
        *(__half2*)(ao + glo) = __floats2half2_rn(o_acc[nt][0] * inv_lo, o_acc[nt][1] * inv_lo);
        *(__half2*)(ao + ghi) = __floats2half2_rn(o_acc[nt][2] * inv_hi, o_acc[nt][3] * inv_hi);
    }
}

// ---------------- launch ----------------
extern "C" void kernel_launch(void* const* d_in, const int* in_sizes, int n_in,
                              void* d_out, int out_size)
{
    (void)in_sizes; (void)n_in; (void)out_size;
    const float* x    = (const float*)d_in[0];
    const float* cosb = (const float*)d_in[1];
    const float* sinb = (const float*)d_in[2];
    const float* Wq   = (const float*)d_in[3];
    const float* Wk   = (const float*)d_in[4];
    const float* Wv   = (const float*)d_in[5];
    const float* Wo   = (const float*)d_in[6];
    float* out = (float*)d_out;

    float* qkv;
    cudaGetSymbolAddress((void**)&qkv, g_qkv);
    __half *x16, *wp16, *wo16, *ao16, *q16, *k16, *v16;
    cudaGetSymbolAddress((void**)&x16,  g_x16);
    cudaGetSymbolAddress((void**)&wp16, g_wp16);
    cudaGetSymbolAddress((void**)&wo16, g_wo16);
    cudaGetSymbolAddress((void**)&ao16, g_ao16);
    cudaGetSymbolAddress((void**)&q16,  g_q16);
    cudaGetSymbolAddress((void**)&k16,  g_k16);
    cudaGetSymbolAddress((void**)&v16,  g_v16);

    const int M = MSZ_;   // 4096
    cudaFuncSetAttribute(gemm_f16, cudaFuncAttributeMaxDynamicSharedMemorySize, GEMM_SMEM);
    cudaFuncSetAttribute(attn_mma, cudaFuncAttributeMaxDynamicSharedMemorySize, ATTN_SMEM);

    // 1) fused fp16 conversions (x, Wq|Wk|Wv packed, Wo)
    conv_all<<<CVT_TOTAL4 / 256, 256>>>(x, Wq, Wk, Wv, Wo, x16, wp16, wo16);

    // 2) fused QKV projection (R11-exact GEMM)
    gemm_f16<<<dim3(NQKV_ / 128, M / 128), 256, GEMM_SMEM>>>(x16, wp16, qkv, NQKV_, E_);

    // 3) V convert + fused rope+rms for Q and K
    conv_v<<<(M * 128 + 255) / 256, 256>>>(qkv, v16);
    rope_rms_all<<<M * (H_ + KV_), 128>>>(qkv, q16, k16, cosb, sinb);

    // 4) attention
    attn_mma<<<dim3(S_ / 128, H_, B_), 256, ATTN_SMEM>>>(q16, k16, v16, ao16);

    // 5) output projection
    gemm_f16<<<dim3(E_ / 128, M / 128), 256, GEMM_SMEM>>>(ao16, wo16, out, E_, NQ_);
}

// round 14
// speedup vs baseline: 1.6446x; 1.0840x over previous
#include <cuda_runtime.h>
#include <cuda_fp16.h>
#include <cstdint>

#define B_   2
#define S_   2048
#define E_   2048
#define H_   16
#define KV_  4
#define D_   128
#define WIN_ 1024

#define MSZ_ (B_ * S_)     // 4096
#define NQ_  (H_ * D_)     // 2048
#define NKV_ (KV_ * D_)    // 512
#define NQKV_ (NQ_ + 2 * NKV_)   // 3072

// ---------------- scratch ----------------
__device__ float g_qkv[(size_t)MSZ_ * NQKV_];   // packed [M, q|k|v] fp32

__device__ __half g_x16 [(size_t)MSZ_ * E_];
__device__ __half g_wp16[(size_t)NQKV_ * E_];   // packed Wq|Wk|Wv
__device__ __half g_wo16[(size_t)E_ * NQ_];
__device__ __half g_ao16[(size_t)MSZ_ * NQ_];
__device__ __half g_q16 [(size_t)MSZ_ * NQ_];
__device__ __half g_k16 [(size_t)MSZ_ * NKV_];
__device__ __half g_v16 [(size_t)MSZ_ * NKV_];

// ---------------- helpers ----------------
__device__ __forceinline__ uint32_t smem_u32(const void* p) {
    uint32_t a;
    asm("{ .reg .u64 t; cvta.to.shared.u64 t, %1; cvt.u32.u64 %0, t; }" : "=r"(a) : "l"(p));
    return a;
}
__device__ __forceinline__ void cpasync16(uint32_t dst, const void* src) {
    asm volatile("cp.async.cg.shared.global [%0], [%1], 16;" :: "r"(dst), "l"(src));
}
#define CP_COMMIT()  asm volatile("cp.async.commit_group;" ::: "memory")
#define CP_WAIT(n)   asm volatile("cp.async.wait_group %0;" :: "n"(n) : "memory")

__device__ __forceinline__ void ldsm4(uint32_t* r, uint32_t addr) {
    asm volatile("ldmatrix.sync.aligned.m8n8.x4.shared.b16 {%0,%1,%2,%3}, [%4];"
                 : "=r"(r[0]), "=r"(r[1]), "=r"(r[2]), "=r"(r[3]) : "r"(addr));
}
__device__ __forceinline__ void ldsm2(uint32_t* r, uint32_t addr) {
    asm volatile("ldmatrix.sync.aligned.m8n8.x2.shared.b16 {%0,%1}, [%2];"
                 : "=r"(r[0]), "=r"(r[1]) : "r"(addr));
}
__device__ __forceinline__ void ldsm4t(uint32_t* r, uint32_t addr) {
    asm volatile("ldmatrix.sync.aligned.m8n8.x4.trans.shared.b16 {%0,%1,%2,%3}, [%4];"
                 : "=r"(r[0]), "=r"(r[1]), "=r"(r[2]), "=r"(r[3]) : "r"(addr));
}
__device__ __forceinline__ void mma16816h(float* d, const uint32_t* a, const uint32_t* b) {
    asm volatile("mma.sync.aligned.m16n8k16.row.col.f32.f16.f16.f32 "
                 "{%0,%1,%2,%3}, {%4,%5,%6,%7}, {%8,%9}, {%0,%1,%2,%3};"
                 : "+f"(d[0]), "+f"(d[1]), "+f"(d[2]), "+f"(d[3])
                 : "r"(a[0]), "r"(a[1]), "r"(a[2]), "r"(a[3]), "r"(b[0]), "r"(b[1]));
}

// ---------------- fused fp32 -> fp16 conversion for all inputs ----------------
#define CVT_TOTAL4 4718592
__global__ void conv_all(const float* __restrict__ x,  const float* __restrict__ Wq,
                         const float* __restrict__ Wk, const float* __restrict__ Wv,
                         const float* __restrict__ Wo,
                         __half* __restrict__ x16, __half* __restrict__ wp16,
                         __half* __restrict__ wo16)
{
    int i = blockIdx.x * 256 + threadIdx.x;
    const float* s; __half* d; int j;
    if (i < 2097152)      { s = x;  d = x16;            j = i; }
    else if (i < 3145728) { s = Wq; d = wp16;           j = i - 2097152; }
    else if (i < 3407872) { s = Wk; d = wp16 + 4194304; j = i - 3145728; }
    else if (i < 3670016) { s = Wv; d = wp16 + 5242880; j = i - 3407872; }
    else                  { s = Wo; d = wo16;           j = i - 3670016; }
    float4 v = ((const float4*)s)[j];
    ((__half2*)d)[j * 2]     = __floats2half2_rn(v.x, v.y);
    ((__half2*)d)[j * 2 + 1] = __floats2half2_rn(v.z, v.w);
}

// ---------------- warp-per-row: RoPE+RMS for Q,K and fp16 convert for V ----------------
// global warp id = row; segments: [0, MSZ*H) Q | [+, MSZ*KV) K | [+, MSZ*KV) V
#define PREP_ROWS (MSZ_ * (H_ + 2 * KV_))    // 98304
__global__ void __launch_bounds__(256)
prep_qkv(const float* __restrict__ qkv,
         __half* __restrict__ q16, __half* __restrict__ k16, __half* __restrict__ v16,
         const float* __restrict__ cosb, const float* __restrict__ sinb)
{
    const int gw   = blockIdx.x * 8 + (threadIdx.x >> 5);
    const int lane = threadIdx.x & 31;

    if (gw >= MSZ_ * (H_ + KV_)) {
        // V convert: plain fp32 -> fp16
        int r3 = gw - MSZ_ * (H_ + KV_);
        int bs = r3 / KV_, hh = r3 - bs * KV_;
        const float* src = qkv + (size_t)bs * NQKV_ + (NQ_ + NKV_) + hh * D_;
        float4 v = *(const float4*)(src + lane * 4);
        __half* dst = v16 + (size_t)r3 * D_ + lane * 4;
        *(__half2*)(dst)     = __floats2half2_rn(v.x, v.y);
        *(__half2*)(dst + 2) = __floats2half2_rn(v.z, v.w);
        return;
    }

    int bs, hh, coloff, orow;
    __half* out;
    if (gw < MSZ_ * H_) {
        bs = gw / H_;  hh = gw - bs * H_;  coloff = 0;   out = q16; orow = gw;
    } else {
        int r2 = gw - MSZ_ * H_;
        bs = r2 / KV_; hh = r2 - bs * KV_; coloff = NQ_; out = k16; orow = r2;
    }
    const int s = bs % S_;
    const float* p = qkv + (size_t)bs * NQKV_ + coloff + hh * D_;
    const int dh0 = lane * 2;

    float2 a  = *(const float2*)(p + dh0);
    float2 b2 = *(const float2*)(p + dh0 + 64);
    float2 c  = *(const float2*)(cosb + s * 64 + dh0);
    float2 sn = *(const float2*)(sinb + s * 64 + dh0);

    float v0 = a.x  * c.x + b2.x * sn.x;     // first-half outputs
    float v1 = a.y  * c.y + b2.y * sn.y;
    float v2 = b2.x * c.x - a.x  * sn.x;     // second-half outputs
    float v3 = b2.y * c.y - a.y  * sn.y;

    float sq = v0 * v0 + v1 * v1 + v2 * v2 + v3 * v3;
#pragma unroll
    for (int o = 16; o; o >>= 1) sq += __shfl_xor_sync(0xffffffffu, sq, o);
    float r = rsqrtf(sq * (1.0f / 128.0f) + 1.1920929e-7f);

    __half* dst = out + (size_t)orow * D_;
    *(__half2*)(dst + dh0)      = __floats2half2_rn(v0 * r, v1 * r);
    *(__half2*)(dst + 64 + dh0) = __floats2half2_rn(v2 * r, v3 * r);
}

// ---------------- single-pass fp16 HMMA GEMM (4-stage cp.async pipeline) ----------------
#define GSTRIDE 40
#define GTILE_B (128 * GSTRIDE * 2)          // 10240
#define GSTAGE_B (2 * GTILE_B)               // 20480 (A + B)
#define GEMM_SMEM (4 * GSTAGE_B)             // 81920 -> 2 CTA/SM

__global__ void __launch_bounds__(256)
gemm_f16(const __half* __restrict__ A, const __half* __restrict__ Bw,
         float* __restrict__ C, int N, int K)
{
    extern __shared__ char smem[];
    const uint32_t sb = smem_u32(smem);

    const int tid  = threadIdx.x;
    const int lane = tid & 31, warp = tid >> 5;
    const int wm   = warp >> 2;
    const int wn   = warp & 3;
    const size_t by = (size_t)blockIdx.y * 128;
    const size_t bx = (size_t)blockIdx.x * 128;

    const __half* srcA = A  + by * K;
    const __half* srcB = Bw + bx * K;

    const int r0 = tid >> 2,  c0 = (tid & 3);
    const int r1 = r0 + 64;

    auto issue = [&](int kt, int s) {
        const uint32_t base = sb + (uint32_t)s * GSTAGE_B;
        cpasync16(base + (r0 * GSTRIDE + c0 * 8) * 2, srcA + (size_t)r0 * K + kt * 32 + c0 * 8);
        cpasync16(base + (r1 * GSTRIDE + c0 * 8) * 2, srcA + (size_t)r1 * K + kt * 32 + c0 * 8);
        cpasync16(base + GTILE_B + (r0 * GSTRIDE + c0 * 8) * 2, srcB + (size_t)r0 * K + kt * 32 + c0 * 8);
        cpasync16(base + GTILE_B + (r1 * GSTRIDE + c0 * 8) * 2, srcB + (size_t)r1 * K + kt * 32 + c0 * 8);
    };

    float acc[4][4][4];
#pragma unroll
    for (int mt = 0; mt < 4; ++mt)
#pragma unroll
        for (int nt = 0; nt < 4; ++nt)
#pragma unroll
            for (int e = 0; e < 4; ++e) acc[mt][nt][e] = 0.f;

    const int l2 = lane & 15;
    const int arow = wm * 64 + (lane & 15);
    const int acol0 = (lane >> 4) * 8;
    const int brow = wn * 32 + (l2 & 7);
    const int bcol0 = (l2 >> 3) * 8;

    const int KT = K / 32;
    for (int p = 0; p < 3 && p < KT; ++p) { issue(p, p & 3); CP_COMMIT(); }

    for (int kt = 0; kt < KT; ++kt) {
        if (kt + 2 < KT)      CP_WAIT(2);
        else if (kt + 1 < KT) CP_WAIT(1);
        else                  CP_WAIT(0);
        __syncthreads();
        if (kt + 3 < KT) { issue(kt + 3, (kt + 3) & 3); CP_COMMIT(); }

        const uint32_t base = sb + (uint32_t)(kt & 3) * GSTAGE_B;
#pragma unroll
        for (int kk = 0; kk < 32; kk += 16) {
            uint32_t af[4][4], bf[4][2];
#pragma unroll
            for (int mt = 0; mt < 4; ++mt)
                ldsm4(af[mt], base + ((arow + mt * 16) * GSTRIDE + kk + acol0) * 2);
#pragma unroll
            for (int nt = 0; nt < 4; ++nt)
                ldsm2(bf[nt], base + GTILE_B + ((brow + nt * 8) * GSTRIDE + kk + bcol0) * 2);
#pragma unroll
            for (int mt = 0; mt < 4; ++mt)
#pragma unroll
                for (int nt = 0; nt < 4; ++nt)
                    mma16816h(acc[mt][nt], af[mt], bf[nt]);
        }
    }

#pragma unroll
    for (int mt = 0; mt < 4; ++mt) {
        const int row = (int)by + wm * 64 + mt * 16 + (lane >> 2);
#pragma unroll
        for (int nt = 0; nt < 4; ++nt) {
            const int col = (int)bx + wn * 32 + nt * 8 + (lane & 3) * 2;
            *(float2*)(C + (size_t)row * N + col)       = make_float2(acc[mt][nt][0], acc[mt][nt][1]);
            *(float2*)(C + (size_t)(row + 8) * N + col) = make_float2(acc[mt][nt][2], acc[mt][nt][3]);
        }
    }
}

// ---------------- windowed-causal flash attention (single-pass fp16 HMMA) ----------------
// 128 queries x 1 head per CTA; 8 warps; double-buffered K/V; paired-K ldsm4;
// full-tile fast path skips masking for interior tiles.
#define LDH 136
#define KV_TILE_B (64 * LDH * 2)     // 17408
#define Q_TILE_B  (128 * LDH * 2)    // 34816
#define ATTN_SMEM (Q_TILE_B + 4 * KV_TILE_B)   // 104448

__global__ void __launch_bounds__(256, 2)
attn_mma(const __half* __restrict__ q16, const __half* __restrict__ k16,
         const __half* __restrict__ v16, __half* __restrict__ ao)
{
    extern __shared__ char smem[];
    const uint32_t sb  = smem_u32(smem);
    const uint32_t Qb  = sb;
    const uint32_t kvb = sb + Q_TILE_B;

    const int mblk = blockIdx.x, h = blockIdx.y, b = blockIdx.z;
    const int q0 = mblk * 128;
    const int hk = h >> 2;
    const int tid = threadIdx.x, lane = tid & 31, w = tid >> 5;

    // Q tile load (once)
    for (int i = tid; i < 2048; i += 256) {
        int r = i >> 4, c = (i & 15) * 8;
        cpasync16(Qb + (uint32_t)(r * LDH + c) * 2,
                  q16 + ((size_t)(b * S_ + q0 + r) * H_ + h) * D_ + c);
    }
    CP_COMMIT();

    float o_acc[16][4];
#pragma unroll
    for (int nt = 0; nt < 16; ++nt)
#pragma unroll
        for (int e = 0; e < 4; ++e) o_acc[nt][e] = 0.f;
    float m_lo = -1e30f, m_hi = -1e30f, l_lo = 0.f, l_hi = 0.f;

    const float scale = 0.08838834764831845f;
    const int t_first = (2 * mblk - 16 > 0) ? (2 * mblk - 16) : 0;
    const int t_last  = 2 * mblk + 1;

    auto issue_kv = [&](int t, int s) {
        const uint32_t base = kvb + (uint32_t)s * 2 * KV_TILE_B;
        for (int i = tid; i < 1024; i += 256) {
            int r = i >> 4, c = (i & 15) * 8;
            size_t g = ((size_t)(b * S_ + t * 64 + r) * KV_ + hk) * D_ + c;
            uint32_t o = (uint32_t)(r * LDH + c) * 2;
            cpasync16(base + o, k16 + g);
            cpasync16(base + KV_TILE_B + o, v16 + g);
        }
    };
    issue_kv(t_first, t_first & 1);
    CP_COMMIT();

    const uint32_t a_off = (uint32_t)((w * 16 + (lane & 15)) * LDH + (lane >> 4) * 8) * 2;
    const int kr = (lane & 7) + ((lane >> 4) << 3);
    const int kcsel = ((lane >> 3) & 1) << 3;
    const uint32_t k_off = (uint32_t)(kr * LDH + kcsel) * 2;
    const int i_lo = q0 + w * 16 + (lane >> 2);
    const int i_hi = i_lo + 8;
    const int wi_min = q0 + w * 16;         // warp's min query index
    const int wi_max = wi_min + 15;         // warp's max query index

    for (int t = t_first; t <= t_last; ++t) {
        const int j0 = t * 64;
        __syncthreads();
        if (t < t_last) { issue_kv(t + 1, (t + 1) & 1); CP_COMMIT(); CP_WAIT(1); }
        else            { CP_WAIT(0); }
        __syncthreads();

        const uint32_t Kb = kvb + (uint32_t)(t & 1) * 2 * KV_TILE_B;
        const uint32_t Vb = Kb + KV_TILE_B;

        // ---- S = Q K^T ----
        float s[8][4];
#pragma unroll
        for (int nt = 0; nt < 8; ++nt)
#pragma unroll
            for (int e = 0; e < 4; ++e) s[nt][e] = 0.f;

#pragma unroll
        for (int kk = 0; kk < 128; kk += 16) {
            uint32_t aq[4];
            ldsm4(aq, Qb + a_off + kk * 2);
#pragma unroll
            for (int nt = 0; nt < 8; nt += 2) {
                uint32_t bk[4];
                ldsm4(bk, Kb + k_off + (uint32_t)(nt * 8 * LDH + kk) * 2);
                mma16816h(s[nt],     aq, bk);
                mma16816h(s[nt + 1], aq, bk + 2);
            }
        }

        // ---- masked online softmax ----
        float mx_lo = -1e30f, mx_hi = -1e30f;
        const bool fullt = (j0 + 63 <= wi_min) && (wi_max - j0 < WIN_);
        if (fullt) {
#pragma unroll
            for (int nt = 0; nt < 8; ++nt) {
                s[nt][0] *= scale; s[nt][1] *= scale;
                s[nt][2] *= scale; s[nt][3] *= scale;
                mx_lo = fmaxf(mx_lo, fmaxf(s[nt][0], s[nt][1]));
                mx_hi = fmaxf(mx_hi, fmaxf(s[nt][2], s[nt][3]));
            }
        } else {
#pragma unroll
            for (int nt = 0; nt < 8; ++nt) {
                int jb = j0 + nt * 8 + (lane & 3) * 2;
                bool v0 = (jb     <= i_lo) && (i_lo - jb     < WIN_);
                bool v1 = (jb + 1 <= i_lo) && (i_lo - jb - 1 < WIN_);
                bool v2 = (jb     <= i_hi) && (i_hi - jb     < WIN_);
                bool v3 = (jb + 1 <= i_hi) && (i_hi - jb - 1 < WIN_);
                s[nt][0] = v0 ? s[nt][0] * scale : -1e30f;
                s[nt][1] = v1 ? s[nt][1] * scale : -1e30f;
                s[nt][2] = v2 ? s[nt][2] * scale : -1e30f;
                s[nt][3] = v3 ? s[nt][3] * scale : -1e30f;
                mx_lo = fmaxf(mx_lo, fmaxf(s[nt][0], s[nt][1]));
                mx_hi = fmaxf(mx_hi, fmaxf(s[nt][2], s[nt][3]));
            }
        }
        mx_lo = fmaxf(mx_lo, __shfl_xor_sync(0xffffffffu, mx_lo, 1));
        mx_lo = fmaxf(mx_lo, __shfl_xor_sync(0xffffffffu, mx_lo, 2));
        mx_hi = fmaxf(mx_hi, __shfl_xor_sync(0xffffffffu, mx_hi, 1));
        mx_hi = fmaxf(mx_hi, __shfl_xor_sync(0xffffffffu, mx_hi, 2));

        float mn_lo = fmaxf(m_lo, mx_lo), mn_hi = fmaxf(m_hi, mx_hi);
        float al_lo = __expf(m_lo - mn_lo), al_hi = __expf(m_hi - mn_hi);
        float sum_lo = 0.f, sum_hi = 0.f;
#pragma unroll
        for (int nt = 0; nt < 8; ++nt) {
            s[nt][0] = __expf(s[nt][0] - mn_lo);
            s[nt][1] = __expf(s[nt][1] - mn_lo);
            s[nt][2] = __expf(s[nt][2] - mn_hi);
            s[nt][3] = __expf(s[nt][3] - mn_hi);
            sum_lo += s[nt][0] + s[nt][1];
            sum_hi += s[nt][2] + s[nt][3];
        }
        sum_lo += __shfl_xor_sync(0xffffffffu, sum_lo, 1);
        sum_lo += __shfl_xor_sync(0xffffffffu, sum_lo, 2);
        sum_hi += __shfl_xor_sync(0xffffffffu, sum_hi, 1);
        sum_hi += __shfl_xor_sync(0xffffffffu, sum_hi, 2);
        l_lo = l_lo * al_lo + sum_lo;  m_lo = mn_lo;
        l_hi = l_hi * al_hi + sum_hi;  m_hi = mn_hi;
#pragma unroll
        for (int nt = 0; nt < 16; ++nt) {
            o_acc[nt][0] *= al_lo; o_acc[nt][1] *= al_lo;
            o_acc[nt][2] *= al_hi; o_acc[nt][3] *= al_hi;
        }

        // ---- O += P V ----
#pragma unroll
        for (int kc = 0; kc < 4; ++kc) {
            uint32_t ap[4];
            __half2 p0 = __floats2half2_rn(s[2*kc][0],   s[2*kc][1]);
            __half2 p1 = __floats2half2_rn(s[2*kc][2],   s[2*kc][3]);
            __half2 p2 = __floats2half2_rn(s[2*kc+1][0], s[2*kc+1][1]);
            __half2 p3 = __floats2half2_rn(s[2*kc+1][2], s[2*kc+1][3]);
            ap[0] = *(uint32_t*)&p0; ap[1] = *(uint32_t*)&p1;
            ap[2] = *(uint32_t*)&p2; ap[3] = *(uint32_t*)&p3;

            uint32_t vr = (uint32_t)(kc * 16 + (lane & 7) + ((lane >> 3) & 1) * 8) * LDH
                        + (uint32_t)((lane >> 4) * 8);
#pragma unroll
            for (int dt = 0; dt < 8; ++dt) {
                uint32_t bv[4];
                ldsm4t(bv, Vb + (vr + dt * 16) * 2);
                mma16816h(o_acc[2*dt],   ap, bv);
                mma16816h(o_acc[2*dt+1], ap, bv + 2);
            }
        }
    }

    // ---- epilogue: normalize, write fp16 ----
    float inv_lo = 1.0f / l_lo, inv_hi = 1.0f / l_hi;
#pragma unroll
    for (int nt = 0; nt < 16; ++nt) {
        int c = nt * 8 + (lane & 3) * 2;
        size_t glo = ((size_t)(b * S_ + i_lo) * H_ + h) * D_ + c;
        size_t ghi = ((size_t)(b * S_ + i_hi) * H_ + h) * D_ + c;
        *(__half2*)(ao + glo) = __floats2half2_rn(o_acc[nt][0] * inv_lo, o_acc[nt][1] * inv_lo);
        *(__half2*)(ao + ghi) = __floats2half2_rn(o_acc[nt][2] * inv_hi, o_acc[nt][3] * inv_hi);
    }
}

// ---------------- launch ----------------
extern "C" void kernel_launch(void* const* d_in, const int* in_sizes, int n_in,
                              void* d_out, int out_size)
{
    (void)in_sizes; (void)n_in; (void)out_size;
    const float* x    = (const float*)d_in[0];
    const float* cosb = (const float*)d_in[1];
    const float* sinb = (const float*)d_in[2];
    const float* Wq   = (const float*)d_in[3];
    const float* Wk   = (const float*)d_in[4];
    const float* Wv   = (const float*)d_in[5];
    const float* Wo   = (const float*)d_in[6];
    float* out = (float*)d_out;

    float* qkv;
    cudaGetSymbolAddress((void**)&qkv, g_qkv);
    __half *x16, *wp16, *wo16, *ao16, *q16, *k16, *v16;
    cudaGetSymbolAddress((void**)&x16,  g_x16);
    cudaGetSymbolAddress((void**)&wp16, g_wp16);
    cudaGetSymbolAddress((void**)&wo16, g_wo16);
    cudaGetSymbolAddress((void**)&ao16, g_ao16);
    cudaGetSymbolAddress((void**)&q16,  g_q16);
    cudaGetSymbolAddress((void**)&k16,  g_k16);
    cudaGetSymbolAddress((void**)&v16,  g_v16);

    const int M = MSZ_;   // 4096
    cudaFuncSetAttribute(gemm_f16, cudaFuncAttributeMaxDynamicSharedMemorySize, GEMM_SMEM);
    cudaFuncSetAttribute(attn_mma, cudaFuncAttributeMaxDynamicSharedMemorySize, ATTN_SMEM);

    // 1) fused fp16 conversions (x, Wq|Wk|Wv packed, Wo)
    conv_all<<<CVT_TOTAL4 / 256, 256>>>(x, Wq, Wk, Wv, Wo, x16, wp16, wo16);

    // 2) fused QKV projection
    gemm_f16<<<dim3(NQKV_ / 128, M / 128), 256, GEMM_SMEM>>>(x16, wp16, qkv, NQKV_, E_);

    // 3) warp-per-row rope+rms (Q,K) + V convert, one launch
    prep_qkv<<<PREP_ROWS / 8, 256>>>(qkv, q16, k16, v16, cosb, sinb);

    // 4) attention
    attn_mma<<<dim3(S_ / 128, H_, B_), 256, ATTN_SMEM>>>(q16, k16, v16, ao16);

    // 5) output projection
    gemm_f16<<<dim3(E_ / 128, M / 128), 256, GEMM_SMEM>>>(ao16, wo16, out, E_, NQ_);
}